// round 5
// baseline (speedup 1.0000x reference)
#include <cuda_runtime.h>
#include <cstdint>

// SDF_75806172774865 — R5: cp.async.bulk (UBLKCP) staging + mbarrier pipeline,
// scalar-LDS compute (R3 shape), 256 thr, __launch_bounds__(256,6).
// points: (N,P,3) f32 ; v,vn: (N,P,K,3) f32 ; sr: (N,P,K) f32 ; out: (N,) f32

#define K_FIX 60
#define SLAB 8
#define THREADS 256
#define NWARPS 8
#define ROWF (K_FIX * 3)                       // 180 floats per v/vn row
#define OFF_VN (SLAB * ROWF)                   // 1440
#define OFF_SR (2 * SLAB * ROWF)               // 2880
#define BUF_FLOATS (2 * SLAB * ROWF + SLAB * K_FIX)  // 3360 floats = 13440 B
#define NMAX 8

__device__ __forceinline__ uint32_t smem_u32(const void* p) {
    return (uint32_t)__cvta_generic_to_shared(p);
}

__device__ __forceinline__ void mbar_init(uint32_t mbar, uint32_t count) {
    asm volatile("mbarrier.init.shared::cta.b64 [%0], %1;" :: "r"(mbar), "r"(count) : "memory");
}
__device__ __forceinline__ void mbar_expect_tx(uint32_t mbar, uint32_t bytes) {
    asm volatile("mbarrier.arrive.expect_tx.shared::cta.b64 _, [%0], %1;"
                 :: "r"(mbar), "r"(bytes) : "memory");
}
__device__ __forceinline__ void mbar_wait(uint32_t mbar, uint32_t parity) {
    asm volatile(
        "{\n\t.reg .pred P;\n\t"
        "WL_%=:\n\t"
        "mbarrier.try_wait.parity.acquire.cta.shared::cta.b64 P, [%0], %1, 0x989680;\n\t"
        "@P bra WD_%=;\n\t"
        "bra WL_%=;\n\t"
        "WD_%=:\n\t}"
        :: "r"(mbar), "r"(parity) : "memory");
}
__device__ __forceinline__ void bulk_g2s(uint32_t dst_smem, const void* src, uint32_t bytes,
                                         uint32_t mbar) {
    asm volatile(
        "cp.async.bulk.shared::cta.global.mbarrier::complete_tx::bytes [%0], [%1], %2, [%3];"
        :: "r"(dst_smem), "l"(src), "r"(bytes), "r"(mbar) : "memory");
}

__global__ void sdf_zero_kernel(float* __restrict__ out, int n) {
    int i = blockIdx.x * blockDim.x + threadIdx.x;
    if (i < n) out[i] = 0.0f;
}

__global__ __launch_bounds__(THREADS, 6)
void sdf_kernel(const float* __restrict__ points,
                const float* __restrict__ v,
                const float* __restrict__ vn,
                const float* __restrict__ sr,
                float* __restrict__ out,
                int total_points, int P, int N,
                int total_slabs, int slabs_per_block) {
    __shared__ __align__(16) float s_buf[2][BUF_FLOATS];
    __shared__ float s_acc[NWARPS * NMAX];
    __shared__ __align__(8) unsigned long long s_mbar[2];

    const int tid  = threadIdx.x;
    const int warp = tid >> 5;
    const int lane = tid & 31;

    const int s0 = blockIdx.x * slabs_per_block;
    const int s1 = min(s0 + slabs_per_block, total_slabs);
    if (s0 >= s1) return;

    if (tid == 0) {
        mbar_init(smem_u32(&s_mbar[0]), 1);
        mbar_init(smem_u32(&s_mbar[1]), 1);
    }
    if (tid < NWARPS * NMAX) s_acc[tid] = 0.0f;
    asm volatile("fence.proxy.async.shared::cta;" ::: "memory");
    __syncthreads();

    int ph0 = 0, ph1 = 0;

    // Issue bulk staging of slab s into buffer b (thread 0 only).
    auto issue = [&](int s, int b) {
        const int gp0  = s * SLAB;
        const int npts = min(SLAB, total_points - gp0);
        const uint32_t mb = smem_u32(&s_mbar[b]);
        const uint32_t bv  = (uint32_t)npts * (ROWF * 4);   // 720 B/pt
        const uint32_t bsr = (uint32_t)npts * (K_FIX * 4);  // 240 B/pt
        mbar_expect_tx(mb, bv + bv + bsr);
        float* buf = s_buf[b];
        bulk_g2s(smem_u32(buf),           v  + (size_t)gp0 * ROWF,  bv,  mb);
        bulk_g2s(smem_u32(buf + OFF_VN),  vn + (size_t)gp0 * ROWF,  bv,  mb);
        bulk_g2s(smem_u32(buf + OFF_SR),  sr + (size_t)gp0 * K_FIX, bsr, mb);
    };

    if (tid == 0) issue(s0, s0 & 1);

    for (int s = s0; s < s1; s++) {
        const int cur = s & 1;
        // Stage next slab into the other buffer (it was computed at s-1 and
        // released by the trailing __syncthreads).
        if (tid == 0 && s + 1 < s1) issue(s + 1, cur ^ 1);

        // Prefetch this warp's point coords (broadcast LDG) — latency hides
        // under the mbarrier wait below.
        const int gp = s * SLAB + warp;
        const bool pvalid = (gp < total_points);
        float px = 0.f, py = 0.f, pz = 0.f;
        if (pvalid) {
            px = __ldg(points + (size_t)gp * 3 + 0);
            py = __ldg(points + (size_t)gp * 3 + 1);
            pz = __ldg(points + (size_t)gp * 3 + 2);
        }

        if (cur == 0) { mbar_wait(smem_u32(&s_mbar[0]), ph0); ph0 ^= 1; }
        else          { mbar_wait(smem_u32(&s_mbar[1]), ph1); ph1 ^= 1; }

        if (pvalid) {
            const float* __restrict__ buf   = s_buf[cur];
            const float* __restrict__ vrow  = buf + warp * ROWF;
            const float* __restrict__ vnrow = buf + OFF_VN + warp * ROWF;
            const float* __restrict__ srow  = buf + OFF_SR + warp * K_FIX;

            float num = 0.0f, den = 0.0f;
            #pragma unroll
            for (int kk = 0; kk < 2; kk++) {
                const int k = lane + kk * 32;
                if (k < K_FIX) {
                    const float vx = vrow[3 * k + 0];
                    const float vy = vrow[3 * k + 1];
                    const float vz = vrow[3 * k + 2];
                    const float nx = vnrow[3 * k + 0];
                    const float ny = vnrow[3 * k + 1];
                    const float nz = vnrow[3 * k + 2];
                    const float sv = srow[k];

                    const float dx = px - vx;
                    const float dy = py - vy;
                    const float dz = pz - vz;
                    const float d2 = fmaf(dx, dx, fmaf(dy, dy, dz * dz));

                    const float w   = 1.0f - d2 * __frcp_rn(sv);
                    const float w2  = w * w;
                    const float phi = (d2 < sv) ? (w2 * w2) : 1e-18f;

                    const float dot = fmaf(nx, dx, fmaf(ny, dy, nz * dz));
                    num = fmaf(phi, dot, num);
                    den += phi;
                }
            }
            #pragma unroll
            for (int o = 16; o > 0; o >>= 1) {
                num += __shfl_xor_sync(0xffffffffu, num, o);
                den += __shfl_xor_sync(0xffffffffu, den, o);
            }
            if (lane == 0) {
                const float sdf = num / den;
                const int ni = gp / P;
                if (ni < NMAX) s_acc[warp * NMAX + ni] += sdf * sdf;
                else           atomicAdd(&out[ni], sdf * sdf);
            }
        }
        __syncthreads();   // release buf[cur] for restaging at s+1
    }

    if (tid < N && tid < NMAX) {
        float sum = 0.0f;
        #pragma unroll
        for (int w = 0; w < NWARPS; w++) sum += s_acc[w * NMAX + tid];
        atomicAdd(&out[tid], sum);
    }
}

extern "C" void kernel_launch(void* const* d_in, const int* in_sizes, int n_in,
                              void* d_out, int out_size) {
    const float* points = (const float*)d_in[0];
    const float* v      = (const float*)d_in[1];
    const float* vn     = (const float*)d_in[2];
    const float* sr     = (const float*)d_in[3];
    float* out = (float*)d_out;

    const int total_points = in_sizes[0] / 3;  // N*P
    const int N = out_size;
    const int P = total_points / N;

    sdf_zero_kernel<<<1, 32>>>(out, out_size);

    const int total_slabs = (total_points + SLAB - 1) / SLAB;
    const int max_blocks  = 148 * 6;   // one resident wave at 6 blocks/SM
    const int grid        = total_slabs < max_blocks ? total_slabs : max_blocks;
    const int spb         = (total_slabs + grid - 1) / grid;

    sdf_kernel<<<grid, THREADS>>>(points, v, vn, sr, out,
                                  total_points, P, N, total_slabs, spb);
}

// round 6
// speedup vs baseline: 1.5612x; 1.5612x over previous
#include <cuda_runtime.h>
#include <cstdint>

// SDF_75806172774865 — R6: R3 cp.async double-buffer + 2-points/warp LDS.128
// compute, 16-point slabs, 256 threads, launch_bounds(256,4).
// points: (N,P,3) f32 ; v,vn: (N,P,K,3) f32 ; sr: (N,P,K) f32 ; out: (N,) f32

#define K_FIX 60
#define SLAB 16                        // points per slab (2 per warp)
#define THREADS 256
#define NWARPS 8
#define ROWF (K_FIX * 3)               // 180 floats per v/vn row
#define OFF_VN (SLAB * ROWF)           // 2880
#define OFF_SR (2 * SLAB * ROWF)       // 5760
#define OFF_PT (OFF_SR + SLAB * K_FIX) // 6720
#define BUF_FLOATS (OFF_PT + SLAB * 3) // 6768 floats = 27072 B
#define V4  (SLAB * ROWF / 4)          // 720 float4 per slab for v (and vn)
#define SR4 (SLAB * K_FIX / 4)         // 240
#define PT4 (SLAB * 3 / 4)             // 12
#define NMAX 8

__device__ __forceinline__ void cp_async16(void* smem_ptr, const void* gptr) {
    uint32_t sa = (uint32_t)__cvta_generic_to_shared(smem_ptr);
    asm volatile("cp.async.cg.shared.global [%0], [%1], 16;" :: "r"(sa), "l"(gptr));
}
#define CP_COMMIT() asm volatile("cp.async.commit_group;")
#define CP_WAIT1()  asm volatile("cp.async.wait_group 1;")
#define CP_WAIT0()  asm volatile("cp.async.wait_group 0;")

__global__ void sdf_zero_kernel(float* __restrict__ out, int n) {
    int i = blockIdx.x * blockDim.x + threadIdx.x;
    if (i < n) out[i] = 0.0f;
}

__device__ __forceinline__ void stage_slab(
    float* __restrict__ buf,
    const float* __restrict__ v, const float* __restrict__ vn,
    const float* __restrict__ sr, const float* __restrict__ points,
    int slab, int tid, int total_points)
{
    const int gp0 = slab * SLAB;
    const float4* gv  = (const float4*)(v      + (size_t)gp0 * ROWF);
    const float4* gvn = (const float4*)(vn     + (size_t)gp0 * ROWF);
    const float4* gsr = (const float4*)(sr     + (size_t)gp0 * K_FIX);
    const float4* gpt = (const float4*)(points + (size_t)gp0 * 3);
    float4* sv  = (float4*)buf;
    float4* svn = (float4*)(buf + OFF_VN);
    float4* ssr = (float4*)(buf + OFF_SR);
    float4* spt = (float4*)(buf + OFF_PT);

    const int npts = min(SLAB, total_points - gp0);
    if (npts == SLAB) {
        #pragma unroll
        for (int it = 0; it < 3; it++) {
            const int i = tid + it * THREADS;
            if (i < V4) cp_async16(sv + i, gv + i);
        }
        #pragma unroll
        for (int it = 0; it < 3; it++) {
            const int i = tid + it * THREADS;
            if (i < V4) cp_async16(svn + i, gvn + i);
        }
        if (tid < SR4) cp_async16(ssr + tid, gsr + tid);
        if (tid < PT4) cp_async16(spt + tid, gpt + tid);
    } else {
        const int nv4  = npts * (ROWF / 4);
        const int nsr4 = npts * (K_FIX / 4);
        const int npt4 = (npts * 3 + 3) / 4;
        #pragma unroll
        for (int it = 0; it < 3; it++) {
            const int i = tid + it * THREADS;
            if (i < nv4) { cp_async16(sv + i, gv + i); cp_async16(svn + i, gvn + i); }
        }
        if (tid < nsr4) cp_async16(ssr + tid, gsr + tid);
        if (tid < npt4) cp_async16(spt + tid, gpt + tid);
    }
}

__device__ __forceinline__ void kstep(float px, float py, float pz,
                                      float vx, float vy, float vz,
                                      float nx, float ny, float nz, float s,
                                      float& num, float& den) {
    const float dx = px - vx;
    const float dy = py - vy;
    const float dz = pz - vz;
    const float d2 = fmaf(dx, dx, fmaf(dy, dy, dz * dz));
    const float w  = 1.0f - d2 * __frcp_rn(s);
    const float w2 = w * w;
    const float phi = (d2 < s) ? (w2 * w2) : 1e-18f;
    const float dot = fmaf(nx, dx, fmaf(ny, dy, nz * dz));
    num = fmaf(phi, dot, num);
    den += phi;
}

__global__ __launch_bounds__(THREADS, 4)
void sdf_kernel(const float* __restrict__ points,
                const float* __restrict__ v,
                const float* __restrict__ vn,
                const float* __restrict__ sr,
                float* __restrict__ out,
                int total_points, int P, int N,
                int total_slabs, int slabs_per_block) {
    __shared__ __align__(16) float s_buf[2][BUF_FLOATS];
    __shared__ float s_acc[NWARPS * NMAX];

    const int tid  = threadIdx.x;
    const int warp = tid >> 5;
    const int lane = tid & 31;
    const int half = lane >> 4;    // 0: point 2w, 1: point 2w+1
    const int sub  = lane & 15;    // 0..14 active (4 ks each), 15 idle

    const int s0 = blockIdx.x * slabs_per_block;
    const int s1 = min(s0 + slabs_per_block, total_slabs);
    if (s0 >= s1) return;

    if (tid < NWARPS * NMAX) s_acc[tid] = 0.0f;

    stage_slab(s_buf[s0 & 1], v, vn, sr, points, s0, tid, total_points);
    CP_COMMIT();

    for (int s = s0; s < s1; s++) {
        const int cur = s & 1;
        __syncthreads();                 // compute on buf[cur^1] done
        if (s + 1 < s1) {
            stage_slab(s_buf[cur ^ 1], v, vn, sr, points, s + 1, tid, total_points);
            CP_COMMIT();
            CP_WAIT1();                  // slab s resident
        } else {
            CP_WAIT0();
        }
        __syncthreads();

        const float* __restrict__ buf = s_buf[cur];
        const int p   = 2 * warp + half;
        const int gp  = s * SLAB + p;
        const bool pvalid = (gp < total_points);

        float num = 0.0f, den = 0.0f;
        if (pvalid && sub < 15) {
            const float* __restrict__ vrow  = buf + p * ROWF   + sub * 12;
            const float* __restrict__ vnrow = buf + OFF_VN + p * ROWF   + sub * 12;
            const float* __restrict__ srow  = buf + OFF_SR + p * K_FIX  + sub * 4;
            const float* __restrict__ prow  = buf + OFF_PT + p * 3;
            const float px = prow[0], py = prow[1], pz = prow[2];

            // First pair of ks: needs va, vb, na, nb, s4
            const float4 s4 = *(const float4*)srow;
            const float4 va = *(const float4*)(vrow);
            const float4 vb = *(const float4*)(vrow + 4);
            const float4 na = *(const float4*)(vnrow);
            const float4 nb = *(const float4*)(vnrow + 4);
            kstep(px, py, pz, va.x, va.y, va.z, na.x, na.y, na.z, s4.x, num, den);
            kstep(px, py, pz, va.w, vb.x, vb.y, na.w, nb.x, nb.y, s4.y, num, den);
            // Second pair: vc, nc
            const float4 vc = *(const float4*)(vrow + 8);
            const float4 nc = *(const float4*)(vnrow + 8);
            kstep(px, py, pz, vb.z, vb.w, vc.x, nb.z, nb.w, nc.x, s4.z, num, den);
            kstep(px, py, pz, vc.y, vc.z, vc.w, nc.y, nc.z, nc.w, s4.w, num, den);
        }

        // 16-lane half butterfly: full sums land on every lane of each half
        #pragma unroll
        for (int o = 8; o > 0; o >>= 1) {
            num += __shfl_xor_sync(0xffffffffu, num, o);
            den += __shfl_xor_sync(0xffffffffu, den, o);
        }
        const float sdf  = fdividef(num, den);
        const float sdf2 = pvalid ? (sdf * sdf) : 0.0f;
        const float sdf2B = __shfl_sync(0xffffffffu, sdf2, 16);

        if (lane == 0) {
            const int gpA = s * SLAB + 2 * warp;
            if (gpA < total_points) {
                int niA = 0;
                while (gpA >= (niA + 1) * P) niA++;
                float add = sdf2;
                if (gpA + 1 < total_points) {
                    const int niB = niA + ((gpA + 1) >= (niA + 1) * P ? 1 : 0);
                    if (niB == niA) add += sdf2B;
                    else s_acc[warp * NMAX + niB] += sdf2B;
                }
                s_acc[warp * NMAX + niA] += add;
            }
        }
    }

    __syncthreads();
    if (tid < N && tid < NMAX) {
        float sum = 0.0f;
        #pragma unroll
        for (int w = 0; w < NWARPS; w++) sum += s_acc[w * NMAX + tid];
        atomicAdd(&out[tid], sum);
    }
}

extern "C" void kernel_launch(void* const* d_in, const int* in_sizes, int n_in,
                              void* d_out, int out_size) {
    const float* points = (const float*)d_in[0];
    const float* v      = (const float*)d_in[1];
    const float* vn     = (const float*)d_in[2];
    const float* sr     = (const float*)d_in[3];
    float* out = (float*)d_out;

    const int total_points = in_sizes[0] / 3;  // N*P
    const int N = out_size;
    const int P = total_points / N;

    sdf_zero_kernel<<<1, 32>>>(out, out_size);

    const int total_slabs = (total_points + SLAB - 1) / SLAB;
    const int max_blocks  = 148 * 4;           // 4 blocks/SM (smem-limited)
    const int grid        = total_slabs < max_blocks ? total_slabs : max_blocks;
    const int spb         = (total_slabs + grid - 1) / grid;

    sdf_kernel<<<grid, THREADS>>>(points, v, vn, sr, out,
                                  total_points, P, N, total_slabs, spb);
}